// round 6
// baseline (speedup 1.0000x reference)
#include <cuda_runtime.h>

#define HWPX (1024*1024)
#define NB 8
#define NA 8
#define NK 16
#define NSEG 17
#define EPSV 1e-4f

// per-batch constant block v4 (floats):
// [0,32)     : per-axis float4: {A0*dxi, A1*dxi, A2*dxi, m2}
// [32,64)    : per-axis float4: {pv0, pv1, pv2, 0}
// [64,320)   : dy[a][lane],  stride 32, lanes >=17 zero
// [320,576)  : c02[a][lane], stride 32, lanes >=17 zero
#define CB_AP   0
#define CB_PV   32
#define CB_DY   64
#define CB_C2   320
#define CB_SIZE 576

__device__ float g_consts[NB * CB_SIZE];

__global__ void precompute_kernel(const float* __restrict__ ys,
                                  const float* __restrict__ A) {
    int b = blockIdx.x;
    int t = threadIdx.x;
    const float* Ab = A + b * 3 * NA;
    float* cb = g_consts + b * CB_SIZE;

    if (t < NA) {
        int a = t;
        float Am[3][NA];
        #pragma unroll
        for (int c = 0; c < 3; c++)
            #pragma unroll
            for (int j = 0; j < NA; j++)
                Am[c][j] = Ab[c * NA + j];

        // M = A * A^T  (3x3)
        float M[3][3];
        #pragma unroll
        for (int i = 0; i < 3; i++)
            #pragma unroll
            for (int j = 0; j < 3; j++) {
                float s = 0.f;
                #pragma unroll
                for (int k = 0; k < NA; k++) s += Am[i][k] * Am[j][k];
                M[i][j] = s;
            }

        // analytic 3x3 inverse
        float c00 = M[1][1]*M[2][2] - M[1][2]*M[2][1];
        float c01 = M[1][2]*M[2][0] - M[1][0]*M[2][2];
        float c02 = M[1][0]*M[2][1] - M[1][1]*M[2][0];
        float det = M[0][0]*c00 + M[0][1]*c01 + M[0][2]*c02;
        float id  = 1.0f / det;
        float inv[3][3];
        inv[0][0] = c00 * id;
        inv[1][0] = c01 * id;
        inv[2][0] = c02 * id;
        inv[0][1] = (M[0][2]*M[2][1] - M[0][1]*M[2][2]) * id;
        inv[1][1] = (M[0][0]*M[2][2] - M[0][2]*M[2][0]) * id;
        inv[2][1] = (M[0][1]*M[2][0] - M[0][0]*M[2][1]) * id;
        inv[0][2] = (M[0][1]*M[1][2] - M[0][2]*M[1][1]) * id;
        inv[1][2] = (M[0][2]*M[1][0] - M[0][0]*M[1][2]) * id;
        inv[2][2] = (M[0][0]*M[1][1] - M[0][1]*M[1][0]) * id;

        // pinv[a][c] = sum_k A[k][a] * inv[k][c]
        float pv[3];
        #pragma unroll
        for (int c = 0; c < 3; c++) {
            float s = 0.f;
            #pragma unroll
            for (int k = 0; k < 3; k++) s += Am[k][a] * inv[k][c];
            pv[c] = s;
        }

        float mn = 0.f, mx = 0.f;
        #pragma unroll
        for (int c = 0; c < 3; c++) {
            float v = Am[c][a];
            mn += fminf(v, 0.f);
            mx += fmaxf(v, 0.f);
        }
        float dx  = (mx + EPSV - mn) / 17.0f;
        float dxi = 1.0f / dx;

        cb[CB_AP + a * 4 + 0] = Am[0][a] * dxi;
        cb[CB_AP + a * 4 + 1] = Am[1][a] * dxi;
        cb[CB_AP + a * 4 + 2] = Am[2][a] * dxi;
        cb[CB_AP + a * 4 + 3] = -mn * dxi;

        cb[CB_PV + a * 4 + 0] = pv[0];
        cb[CB_PV + a * 4 + 1] = pv[1];
        cb[CB_PV + a * 4 + 2] = pv[2];
        cb[CB_PV + a * 4 + 3] = 0.f;

        // ys_full = [mins, ys[0..15], maxs]
        float ysf[18];
        ysf[0]  = mn;
        ysf[17] = mx;
        #pragma unroll
        for (int k = 0; k < NK; k++)
            ysf[k + 1] = ys[(b * NA + a) * NK + k];

        // est = fma(u, dy_k, c02_k);  dy_k = ysf[k+1]-ysf[k],
        // c02_k = ysf[k+1] - (k+1)*dy_k
        #pragma unroll
        for (int l = 0; l < 32; l++) {
            float dy = 0.f, c2 = 0.f;
            if (l < NSEG) {
                dy = ysf[l + 1] - ysf[l];
                c2 = ysf[l + 1] - (float)(l + 1) * dy;
            }
            cb[CB_DY + a * 32 + l] = dy;
            cb[CB_C2 + a * 32 + l] = c2;
        }
    }
}

__global__ __launch_bounds__(256, 4)
void spline_main_kernel(const float* __restrict__ raw, float* __restrict__ out) {
    __shared__ __align__(16) float sc[CB_SIZE];
    const int b = blockIdx.y;
    {
        const float* cb = g_consts + b * CB_SIZE;
        for (int i = threadIdx.x; i < CB_SIZE; i += 256) sc[i] = cb[i];
    }
    __syncthreads();

    const int lid = threadIdx.x & 31;

    // per-lane table registers: lane l holds entry l of each axis table
    float dyr[NA], c2r[NA];
    #pragma unroll
    for (int a = 0; a < NA; a++) {
        dyr[a] = sc[CB_DY + a * 32 + lid];
        c2r[a] = sc[CB_C2 + a * 32 + lid];
    }

    const float4* sap = (const float4*)(sc + CB_AP);
    const float4* spv = (const float4*)(sc + CB_PV);

    const size_t base = (size_t)b * 3 * HWPX;
    const int vidx = blockIdx.x * 256 + threadIdx.x;   // float4 index within plane

    float4 R  = ((const float4*)(raw + base          ))[vidx];
    float4 G  = ((const float4*)(raw + base +   HWPX ))[vidx];
    float4 Bv = ((const float4*)(raw + base + 2*HWPX ))[vidx];

    float rr[4] = {R.x,  R.y,  R.z,  R.w};
    float gg[4] = {G.x,  G.y,  G.z,  G.w};
    float bb[4] = {Bv.x, Bv.y, Bv.z, Bv.w};

    float a0[4], a1[4], a2[4];
    #pragma unroll
    for (int q = 0; q < 4; q++) { a0[q] = 0.f; a1[q] = 0.f; a2[q] = 0.f; }

    #pragma unroll
    for (int a = 0; a < NA; a++) {
        const float4 ap = sap[a];
        const float4 pv = spv[a];
        #pragma unroll
        for (int q = 0; q < 4; q++) {
            // u in [0,17) by construction (EPS margin >> roundoff); trunc handles -eps
            float u = fmaf(rr[q], ap.x, fmaf(gg[q], ap.y, fmaf(bb[q], ap.z, ap.w)));
            int   k = (int)u;
            float dyk = __shfl_sync(0xffffffffu, dyr[a], k);
            float c2k = __shfl_sync(0xffffffffu, c2r[a], k);
            float est = fmaf(u, dyk, c2k);
            a0[q] = fmaf(est, pv.x, a0[q]);
            a1[q] = fmaf(est, pv.y, a1[q]);
            a2[q] = fmaf(est, pv.z, a2[q]);
        }
    }

    ((float4*)(out + base          ))[vidx] = make_float4(a0[0], a0[1], a0[2], a0[3]);
    ((float4*)(out + base +   HWPX ))[vidx] = make_float4(a1[0], a1[1], a1[2], a1[3]);
    ((float4*)(out + base + 2*HWPX ))[vidx] = make_float4(a2[0], a2[1], a2[2], a2[3]);
}

extern "C" void kernel_launch(void* const* d_in, const int* in_sizes, int n_in,
                              void* d_out, int out_size) {
    const float* raw = (const float*)d_in[0];
    const float* ys  = (const float*)d_in[1];
    const float* A   = (const float*)d_in[2];
    float* out = (float*)d_out;

    precompute_kernel<<<NB, 32>>>(ys, A);

    dim3 grid(HWPX / (256 * 4), NB);
    spline_main_kernel<<<grid, 256>>>(raw, out);
}

// round 7
// speedup vs baseline: 1.0919x; 1.0919x over previous
#include <cuda_runtime.h>

#define HWPX (1024*1024)
#define NB 8
#define NA 8
#define NK 16
#define NSEG 17
#define EPSV 1e-4f

// per-batch constant block v5 (floats):
// [0,32)    : per-axis float4: {A0*dxi, A1*dxi, A2*dxi, m2}
// [32,64)   : per-axis float4: {pv0, pv1, pv2, 0}
// [64,336)  : tab[a][k] as float2 (dy, c02), 8*17*2 = 272 floats
#define CB_AP   0
#define CB_PV   32
#define CB_TAB  64
#define CB_SIZE (64 + NA*NSEG*2)   // 336 floats

__device__ float g_consts[NB * CB_SIZE];

__global__ void precompute_kernel(const float* __restrict__ ys,
                                  const float* __restrict__ A) {
    int b = blockIdx.x;
    int t = threadIdx.x;
    const float* Ab = A + b * 3 * NA;
    float* cb = g_consts + b * CB_SIZE;

    if (t < NA) {
        int a = t;
        float Am[3][NA];
        #pragma unroll
        for (int c = 0; c < 3; c++)
            #pragma unroll
            for (int j = 0; j < NA; j++)
                Am[c][j] = Ab[c * NA + j];

        // M = A * A^T  (3x3)
        float M[3][3];
        #pragma unroll
        for (int i = 0; i < 3; i++)
            #pragma unroll
            for (int j = 0; j < 3; j++) {
                float s = 0.f;
                #pragma unroll
                for (int k = 0; k < NA; k++) s += Am[i][k] * Am[j][k];
                M[i][j] = s;
            }

        // analytic 3x3 inverse
        float c00 = M[1][1]*M[2][2] - M[1][2]*M[2][1];
        float c01 = M[1][2]*M[2][0] - M[1][0]*M[2][2];
        float c02 = M[1][0]*M[2][1] - M[1][1]*M[2][0];
        float det = M[0][0]*c00 + M[0][1]*c01 + M[0][2]*c02;
        float id  = 1.0f / det;
        float inv[3][3];
        inv[0][0] = c00 * id;
        inv[1][0] = c01 * id;
        inv[2][0] = c02 * id;
        inv[0][1] = (M[0][2]*M[2][1] - M[0][1]*M[2][2]) * id;
        inv[1][1] = (M[0][0]*M[2][2] - M[0][2]*M[2][0]) * id;
        inv[2][1] = (M[0][1]*M[2][0] - M[0][0]*M[2][1]) * id;
        inv[0][2] = (M[0][1]*M[1][2] - M[0][2]*M[1][1]) * id;
        inv[1][2] = (M[0][2]*M[1][0] - M[0][0]*M[1][2]) * id;
        inv[2][2] = (M[0][0]*M[1][1] - M[0][1]*M[1][0]) * id;

        // pinv[a][c] = sum_k A[k][a] * inv[k][c]
        float pv[3];
        #pragma unroll
        for (int c = 0; c < 3; c++) {
            float s = 0.f;
            #pragma unroll
            for (int k = 0; k < 3; k++) s += Am[k][a] * inv[k][c];
            pv[c] = s;
        }

        float mn = 0.f, mx = 0.f;
        #pragma unroll
        for (int c = 0; c < 3; c++) {
            float v = Am[c][a];
            mn += fminf(v, 0.f);
            mx += fmaxf(v, 0.f);
        }
        float dx  = (mx + EPSV - mn) / 17.0f;
        float dxi = 1.0f / dx;

        // scaled projection coefficients: u = r*A0' + g*A1' + b*A2' + m2
        cb[CB_AP + a * 4 + 0] = Am[0][a] * dxi;
        cb[CB_AP + a * 4 + 1] = Am[1][a] * dxi;
        cb[CB_AP + a * 4 + 2] = Am[2][a] * dxi;
        cb[CB_AP + a * 4 + 3] = -mn * dxi;

        cb[CB_PV + a * 4 + 0] = pv[0];
        cb[CB_PV + a * 4 + 1] = pv[1];
        cb[CB_PV + a * 4 + 2] = pv[2];
        cb[CB_PV + a * 4 + 3] = 0.f;

        // ys_full = [mins, ys[0..15], maxs]
        float ysf[18];
        ysf[0]  = mn;
        ysf[17] = mx;
        #pragma unroll
        for (int k = 0; k < NK; k++)
            ysf[k + 1] = ys[(b * NA + a) * NK + k];

        // est = ys_hi + (u - (k+1))*dy = fma(u, dy, c02)
        #pragma unroll
        for (int k = 0; k < NSEG; k++) {
            float dy   = ysf[k + 1] - ysf[k];
            float c02v = ysf[k + 1] - (float)(k + 1) * dy;
            cb[CB_TAB + (a * NSEG + k) * 2 + 0] = dy;
            cb[CB_TAB + (a * NSEG + k) * 2 + 1] = c02v;
        }
    }
}

__global__ __launch_bounds__(256, 5)
void spline_main_kernel(const float* __restrict__ raw, float* __restrict__ out) {
    __shared__ __align__(16) float sc[CB_SIZE];
    const int b = blockIdx.y;
    {
        const float* cb = g_consts + b * CB_SIZE;
        for (int i = threadIdx.x; i < CB_SIZE; i += 256) sc[i] = cb[i];
    }
    __syncthreads();

    const float4* sap  = (const float4*)(sc + CB_AP);
    const float4* spv  = (const float4*)(sc + CB_PV);
    const float2* stab = (const float2*)(sc + CB_TAB);

    const size_t base = (size_t)b * 3 * HWPX;
    const int vidx = blockIdx.x * 256 + threadIdx.x;   // float4 index within plane

    float4 R  = ((const float4*)(raw + base          ))[vidx];
    float4 G  = ((const float4*)(raw + base +   HWPX ))[vidx];
    float4 Bv = ((const float4*)(raw + base + 2*HWPX ))[vidx];

    float rr[4] = {R.x,  R.y,  R.z,  R.w};
    float gg[4] = {G.x,  G.y,  G.z,  G.w};
    float bb[4] = {Bv.x, Bv.y, Bv.z, Bv.w};

    float a0[4], a1[4], a2[4];
    #pragma unroll
    for (int q = 0; q < 4; q++) { a0[q] = 0.f; a1[q] = 0.f; a2[q] = 0.f; }

    #pragma unroll
    for (int a = 0; a < NA; a++) {
        const float4 ap = sap[a];
        const float4 pv = spv[a];
        const float2* atab = stab + a * NSEG;
        #pragma unroll
        for (int q = 0; q < 4; q++) {
            // u in [0,17) by construction (EPS margin >> roundoff); trunc handles -eps
            float u = fmaf(rr[q], ap.x, fmaf(gg[q], ap.y, fmaf(bb[q], ap.z, ap.w)));
            int   k = (int)u;
            float2 tc = atab[k];
            float est = fmaf(u, tc.x, tc.y);
            a0[q] = fmaf(est, pv.x, a0[q]);
            a1[q] = fmaf(est, pv.y, a1[q]);
            a2[q] = fmaf(est, pv.z, a2[q]);
        }
    }

    ((float4*)(out + base          ))[vidx] = make_float4(a0[0], a0[1], a0[2], a0[3]);
    ((float4*)(out + base +   HWPX ))[vidx] = make_float4(a1[0], a1[1], a1[2], a1[3]);
    ((float4*)(out + base + 2*HWPX ))[vidx] = make_float4(a2[0], a2[1], a2[2], a2[3]);
}

extern "C" void kernel_launch(void* const* d_in, const int* in_sizes, int n_in,
                              void* d_out, int out_size) {
    const float* raw = (const float*)d_in[0];
    const float* ys  = (const float*)d_in[1];
    const float* A   = (const float*)d_in[2];
    float* out = (float*)d_out;

    precompute_kernel<<<NB, 32>>>(ys, A);

    dim3 grid(HWPX / (256 * 4), NB);
    spline_main_kernel<<<grid, 256>>>(raw, out);
}